// round 3
// baseline (speedup 1.0000x reference)
#include <cuda_runtime.h>

#define DIN  128
#define DOUT 128
#define EDIM 16
#define MAXN 50176
#define MAXE 819200
#define BN_EPS 1e-5f

// ---------------- device scratch (static; no runtime allocation) ------------
__device__ float g_x  [MAXN * DOUT];   // feats @ W_rel^T + b_rel
__device__ float g_res[MAXN * DOUT];   // relu(feats @ W_res^T + b_res)
__device__ float g_h  [MAXN * DOUT];   // pre-BN activations
__device__ int   g_cnt[MAXN];          // per-dst degree (histogram)
__device__ int   g_off[MAXN + 1];      // CSR offsets
__device__ int   g_cur[MAXN];          // placement cursors
__device__ int   g_csr_src[MAXE];      // src node per CSR slot
__device__ int   g_csr_eid[MAXE];      // edge id per CSR slot
__device__ float g_sum  [DOUT];
__device__ float g_sumsq[DOUT];
__device__ float g_scale[DOUT];
__device__ float g_shift[DOUT];
__device__ int   g_is64;               // edge_index dtype flag

// ---------------- K0: detect edge_index dtype (int64 vs int32) --------------
__global__ void k0_detect(const unsigned int* __restrict__ ei_words) {
    __shared__ int any_nz;
    if (threadIdx.x == 0) any_nz = 0;
    __syncthreads();
    int nz = 0;
    for (int i = threadIdx.x; i < 1024; i += blockDim.x)
        nz |= (ei_words[2 * i + 1] != 0u);
    if (nz) atomicOr(&any_nz, 1);
    __syncthreads();
    if (threadIdx.x == 0) g_is64 = any_nz ? 0 : 1;
}

// ---------------- K1: fused node GEMMs + counter zeroing ---------------------
__global__ __launch_bounds__(256, 2)
void k1_node_gemm(const float* __restrict__ feats,
                  const float* __restrict__ Wrel, const float* __restrict__ brel,
                  const float* __restrict__ Wres, const float* __restrict__ bres,
                  int N)
{
    __shared__ float fs[32 * 68];    // [k][node] pitch 68
    __shared__ float ws[32 * 260];   // [k][ocol] pitch 260

    const int tid = threadIdx.x;
    const int m0  = blockIdx.x * 64;

    if (tid < 64 && m0 + tid < N) g_cnt[m0 + tid] = 0;
    if (blockIdx.x == 0 && tid < DOUT) { g_sum[tid] = 0.f; g_sumsq[tid] = 0.f; }

    const int o8 = (tid >> 3) * 8;   // output col base (0..248)
    const int n8 = (tid & 7) * 8;    // node base within tile (0..56)

    float acc[8][8];
    #pragma unroll
    for (int oi = 0; oi < 8; oi++) {
        int c = o8 + oi;
        float b = (c < DOUT) ? brel[c] : bres[c - DOUT];
        #pragma unroll
        for (int nj = 0; nj < 8; nj++) acc[oi][nj] = b;
    }

    for (int t = 0; t < DIN / 32; t++) {
        __syncthreads();
        for (int i = tid; i < 64 * 32; i += 256) {
            int kk = i & 31, n = i >> 5;
            int node = m0 + n;
            fs[kk * 68 + n] = (node < N) ? feats[node * DIN + t * 32 + kk] : 0.f;
        }
        for (int i = tid; i < 256 * 32; i += 256) {
            int kk = i & 31, o = i >> 5;
            float v = (o < DOUT) ? Wrel[o * DIN + t * 32 + kk]
                                 : Wres[(o - DOUT) * DIN + t * 32 + kk];
            ws[kk * 260 + o] = v;
        }
        __syncthreads();

        #pragma unroll
        for (int kk = 0; kk < 32; kk++) {
            float4 w0 = *(const float4*)&ws[kk * 260 + o8];
            float4 w1 = *(const float4*)&ws[kk * 260 + o8 + 4];
            float4 f0 = *(const float4*)&fs[kk * 68 + n8];
            float4 f1 = *(const float4*)&fs[kk * 68 + n8 + 4];
            float wv[8] = {w0.x, w0.y, w0.z, w0.w, w1.x, w1.y, w1.z, w1.w};
            float fv[8] = {f0.x, f0.y, f0.z, f0.w, f1.x, f1.y, f1.z, f1.w};
            #pragma unroll
            for (int oi = 0; oi < 8; oi++)
                #pragma unroll
                for (int nj = 0; nj < 8; nj++)
                    acc[oi][nj] += wv[oi] * fv[nj];
        }
    }

    #pragma unroll
    for (int nj = 0; nj < 8; nj++) {
        int node = m0 + n8 + nj;
        if (node >= N) continue;
        #pragma unroll
        for (int oi = 0; oi < 8; oi += 4) {
            int c = o8 + oi;
            float4 v = make_float4(acc[oi][nj], acc[oi+1][nj], acc[oi+2][nj], acc[oi+3][nj]);
            if (c < DOUT) {
                *(float4*)&g_x[node * DOUT + c] = v;
            } else {
                v.x = fmaxf(v.x, 0.f); v.y = fmaxf(v.y, 0.f);
                v.z = fmaxf(v.z, 0.f); v.w = fmaxf(v.w, 0.f);
                *(float4*)&g_res[node * DOUT + (c - DOUT)] = v;
            }
        }
    }
}

// ---------------- K2a: histogram over dst -------------------------------------
__global__ __launch_bounds__(256)
void k_hist(const void* __restrict__ ei_raw, int E)
{
    int e = blockIdx.x * blockDim.x + threadIdx.x;
    if (e >= E) return;
    int d = g_is64 ? (int)((const long long*)ei_raw)[E + e]
                   : ((const int*)ei_raw)[E + e];
    atomicAdd(&g_cnt[d], 1);
}

// ---------------- K2b: exclusive scan (single 1024-thread block) -------------
__global__ __launch_bounds__(1024)
void k_scan(int N)
{
    __shared__ int ps[1024];
    int t = threadIdx.x;
    int chunk = (N + 1023) / 1024;
    int begin = t * chunk;
    int end = begin + chunk; if (end > N) end = N;
    int s = 0;
    for (int i = begin; i < end; i++) s += g_cnt[i];
    ps[t] = s;
    __syncthreads();
    for (int off = 1; off < 1024; off <<= 1) {
        int v = 0;
        if (t >= off) v = ps[t - off];
        __syncthreads();
        if (t >= off) ps[t] += v;
        __syncthreads();
    }
    int run = (t > 0) ? ps[t - 1] : 0;
    for (int i = begin; i < end; i++) {
        int c = g_cnt[i];
        g_off[i] = run;
        g_cur[i] = run;
        run += c;
    }
    if (t == 1023) g_off[N] = ps[1023];
}

// ---------------- K2c: place edges into CSR ----------------------------------
__global__ __launch_bounds__(256)
void k_place(const void* __restrict__ ei_raw, int E)
{
    int e = blockIdx.x * blockDim.x + threadIdx.x;
    if (e >= E) return;
    int s, d;
    if (g_is64) {
        const long long* p = (const long long*)ei_raw;
        s = (int)p[e]; d = (int)p[E + e];
    } else {
        const int* p = (const int*)ei_raw;
        s = p[e]; d = p[E + e];
    }
    int pos = atomicAdd(&g_cur[d], 1);
    g_csr_src[pos] = s;
    g_csr_eid[pos] = e;
}

// ---------------- K2d: pull aggregation fused with combine + BN partials ----
// One warp per node; lane owns 4 output cols. Registers hold agg; lanes 0-15
// accumulate one summed edge_attr component each. Then folded edge-linear +
// relu + residual + g_h store + block BN partial sums.
__global__ __launch_bounds__(256)
void k_pull(const float* __restrict__ eattr,
            const float* __restrict__ We, const float* __restrict__ be,
            int N)
{
    __shared__ float s_sum[128];
    __shared__ float s_sq[128];
    int tid = threadIdx.x;
    if (tid < 128) { s_sum[tid] = 0.f; s_sq[tid] = 0.f; }
    __syncthreads();

    int warp = tid >> 5, lane = tid & 31;
    int n = blockIdx.x * 8 + warp;

    if (n < N) {
        const int j0 = g_off[n], j1 = g_off[n + 1];
        const int c0 = lane * 4;

        float4 acc = make_float4(0.f, 0.f, 0.f, 0.f);
        float ea = 0.f;

        int j = j0;
        // 4-wide unroll: keep 4 independent gathers in flight per warp
        for (; j + 3 < j1; j += 4) {
            int s0 = g_csr_src[j],   s1 = g_csr_src[j+1];
            int s2 = g_csr_src[j+2], s3 = g_csr_src[j+3];
            int e0 = g_csr_eid[j],   e1 = g_csr_eid[j+1];
            int e2 = g_csr_eid[j+2], e3 = g_csr_eid[j+3];
            float4 x0 = *(const float4*)&g_x[(size_t)s0 * DOUT + c0];
            float4 x1 = *(const float4*)&g_x[(size_t)s1 * DOUT + c0];
            float4 x2 = *(const float4*)&g_x[(size_t)s2 * DOUT + c0];
            float4 x3 = *(const float4*)&g_x[(size_t)s3 * DOUT + c0];
            float a0 = 0.f, a1 = 0.f, a2 = 0.f, a3 = 0.f;
            if (lane < EDIM) {
                a0 = eattr[(size_t)e0 * EDIM + lane];
                a1 = eattr[(size_t)e1 * EDIM + lane];
                a2 = eattr[(size_t)e2 * EDIM + lane];
                a3 = eattr[(size_t)e3 * EDIM + lane];
            }
            acc.x += (x0.x + x1.x) + (x2.x + x3.x);
            acc.y += (x0.y + x1.y) + (x2.y + x3.y);
            acc.z += (x0.z + x1.z) + (x2.z + x3.z);
            acc.w += (x0.w + x1.w) + (x2.w + x3.w);
            ea += (a0 + a1) + (a2 + a3);
        }
        for (; j < j1; j++) {
            int s0 = g_csr_src[j];
            int e0 = g_csr_eid[j];
            float4 x0 = *(const float4*)&g_x[(size_t)s0 * DOUT + c0];
            acc.x += x0.x; acc.y += x0.y; acc.z += x0.z; acc.w += x0.w;
            if (lane < EDIM) ea += eattr[(size_t)e0 * EDIM + lane];
        }

        // broadcast summed edge_attr to all lanes
        float eav[EDIM];
        #pragma unroll
        for (int q = 0; q < EDIM; q++) eav[q] = __shfl_sync(0xffffffffu, ea, q);

        const float deg = (float)(j1 - j0);
        float4 b = *(const float4*)&be[c0];
        float4 elin = make_float4(b.x * deg, b.y * deg, b.z * deg, b.w * deg);

        const float4* W4 = (const float4*)We;  // row c: 4 float4 chunks
        #pragma unroll
        for (int q4 = 0; q4 < 4; q4++) {
            float4 w0 = W4[(c0 + 0) * 4 + q4];
            float4 w1 = W4[(c0 + 1) * 4 + q4];
            float4 w2 = W4[(c0 + 2) * 4 + q4];
            float4 w3 = W4[(c0 + 3) * 4 + q4];
            float e0v = eav[q4 * 4 + 0], e1v = eav[q4 * 4 + 1];
            float e2v = eav[q4 * 4 + 2], e3v = eav[q4 * 4 + 3];
            elin.x += w0.x * e0v + w0.y * e1v + w0.z * e2v + w0.w * e3v;
            elin.y += w1.x * e0v + w1.y * e1v + w1.z * e2v + w1.w * e3v;
            elin.z += w2.x * e0v + w2.y * e1v + w2.z * e2v + w2.w * e3v;
            elin.w += w3.x * e0v + w3.y * e1v + w3.z * e2v + w3.w * e3v;
        }

        float4 res = *(const float4*)&g_res[(size_t)n * DOUT + c0];
        float4 h;
        h.x = fmaxf(acc.x + elin.x, 0.f) + res.x;
        h.y = fmaxf(acc.y + elin.y, 0.f) + res.y;
        h.z = fmaxf(acc.z + elin.z, 0.f) + res.z;
        h.w = fmaxf(acc.w + elin.w, 0.f) + res.w;
        *(float4*)&g_h[(size_t)n * DOUT + c0] = h;

        atomicAdd(&s_sum[c0 + 0], h.x);
        atomicAdd(&s_sum[c0 + 1], h.y);
        atomicAdd(&s_sum[c0 + 2], h.z);
        atomicAdd(&s_sum[c0 + 3], h.w);
        atomicAdd(&s_sq[c0 + 0], h.x * h.x);
        atomicAdd(&s_sq[c0 + 1], h.y * h.y);
        atomicAdd(&s_sq[c0 + 2], h.z * h.z);
        atomicAdd(&s_sq[c0 + 3], h.w * h.w);
    }

    __syncthreads();
    if (tid < 128) {
        atomicAdd(&g_sum[tid],   s_sum[tid]);
        atomicAdd(&g_sumsq[tid], s_sq[tid]);
    }
}

// ---------------- K4: finalize BN stats --------------------------------------
__global__ void k4_stats(const float* __restrict__ gamma,
                         const float* __restrict__ beta, int N)
{
    int c = threadIdx.x;
    float invN = 1.f / (float)N;
    float mean = g_sum[c] * invN;
    float var  = g_sumsq[c] * invN - mean * mean;
    float rstd = rsqrtf(var + BN_EPS);
    float sc   = gamma[c] * rstd;
    g_scale[c] = sc;
    g_shift[c] = beta[c] - mean * sc;
}

// ---------------- K5: normalize ----------------------------------------------
__global__ __launch_bounds__(256)
void k5_norm(float* __restrict__ out, int total4)
{
    int idx = blockIdx.x * blockDim.x + threadIdx.x;
    if (idx >= total4) return;
    int c4 = (idx & (DOUT / 4 - 1)) * 4;
    float4 h  = *(const float4*)&g_h[idx * 4];
    float4 sc = *(const float4*)&g_scale[c4];
    float4 sh = *(const float4*)&g_shift[c4];
    float4 o;
    o.x = h.x * sc.x + sh.x;
    o.y = h.y * sc.y + sh.y;
    o.z = h.z * sc.z + sh.z;
    o.w = h.w * sc.w + sh.w;
    ((float4*)out)[idx] = o;
}

// ---------------- launch ------------------------------------------------------
extern "C" void kernel_launch(void* const* d_in, const int* in_sizes, int n_in,
                              void* d_out, int out_size)
{
    const float* feats = (const float*)d_in[0];
    const void*  ei    = d_in[1];
    const float* eattr = (const float*)d_in[2];
    const float* Wrel  = (const float*)d_in[3];
    const float* brel  = (const float*)d_in[4];
    const float* We    = (const float*)d_in[5];
    const float* be    = (const float*)d_in[6];
    const float* Wres  = (const float*)d_in[7];
    const float* bres  = (const float*)d_in[8];
    const float* gamma = (const float*)d_in[9];
    const float* beta  = (const float*)d_in[10];

    const int N = in_sizes[0] / DIN;
    const int E = in_sizes[2] / EDIM;

    k0_detect<<<1, 256>>>((const unsigned int*)ei);
    k1_node_gemm<<<(N + 63) / 64, 256>>>(feats, Wrel, brel, Wres, bres, N);
    k_hist<<<(E + 255) / 256, 256>>>(ei, E);
    k_scan<<<1, 1024>>>(N);
    k_place<<<(E + 255) / 256, 256>>>(ei, E);
    k_pull<<<(N + 7) / 8, 256>>>(eattr, We, be, N);
    k4_stats<<<1, 128>>>(gamma, beta, N);
    int total4 = N * DOUT / 4;
    k5_norm<<<(total4 + 255) / 256, 256>>>((float*)d_out, total4);
}

// round 6
// speedup vs baseline: 1.2042x; 1.2042x over previous
#include <cuda_runtime.h>

#define DIN  128
#define DOUT 128
#define EDIM 16
#define MAXN 50176
#define MAXE 819200
#define BN_EPS 1e-5f
#define SCAN_BLK 512
#define NWARPS (SCAN_BLK / 32)   // 16
#define MAXB1 128                // >= ceil(MAXN/SCAN_BLK) = 98

// ---------------- device scratch (static; no runtime allocation) ------------
__device__ float g_x  [MAXN * DOUT];   // feats @ W_rel^T + b_rel
__device__ float g_res[MAXN * DOUT];   // relu(feats @ W_res^T + b_res)
__device__ float g_h  [MAXN * DOUT];   // pre-BN activations
__device__ float g_ea [MAXN * EDIM];   // scatter-add of edge_attr per dst
__device__ int   g_cnt[MAXN];          // per-dst degree (histogram)
__device__ int   g_off[MAXN + 1];      // CSR offsets
__device__ int   g_cur[MAXN];          // placement cursors
__device__ int   g_csr_src[MAXE];      // src node per CSR slot
__device__ int   g_bsum[MAXB1];        // scan phase-1 block sums
__device__ int   g_boff[MAXB1];        // scan phase-2 block offsets
__device__ float g_sum  [DOUT];
__device__ float g_sumsq[DOUT];
__device__ float g_scale[DOUT];
__device__ float g_shift[DOUT];
__device__ int   g_is64;               // edge_index dtype flag

__device__ __forceinline__ void red_add_v4(float* p, float4 v) {
    asm volatile("red.global.add.v4.f32 [%0], {%1,%2,%3,%4};"
                 :: "l"(p), "f"(v.x), "f"(v.y), "f"(v.z), "f"(v.w)
                 : "memory");
}

// ---------------- K0: detect edge_index dtype (int64 vs int32) --------------
__global__ void k0_detect(const unsigned int* __restrict__ ei_words) {
    __shared__ int any_nz;
    if (threadIdx.x == 0) any_nz = 0;
    __syncthreads();
    int nz = 0;
    for (int i = threadIdx.x; i < 1024; i += blockDim.x)
        nz |= (ei_words[2 * i + 1] != 0u);
    if (nz) atomicOr(&any_nz, 1);
    __syncthreads();
    if (threadIdx.x == 0) g_is64 = any_nz ? 0 : 1;
}

// ---------------- K1: fused node GEMMs + scratch zeroing ---------------------
__global__ __launch_bounds__(256, 2)
void k1_node_gemm(const float* __restrict__ feats,
                  const float* __restrict__ Wrel, const float* __restrict__ brel,
                  const float* __restrict__ Wres, const float* __restrict__ bres,
                  int N)
{
    __shared__ float fs[32 * 68];    // [k][node] pitch 68
    __shared__ float ws[32 * 260];   // [k][ocol] pitch 260

    const int tid = threadIdx.x;
    const int m0  = blockIdx.x * 64;

    if (tid < 64 && m0 + tid < N) g_cnt[m0 + tid] = 0;
    for (int i = tid; i < 64 * EDIM; i += 256) {
        int n = m0 + (i >> 4);
        if (n < N) g_ea[n * EDIM + (i & 15)] = 0.f;
    }
    if (blockIdx.x == 0 && tid < DOUT) { g_sum[tid] = 0.f; g_sumsq[tid] = 0.f; }

    const int o8 = (tid >> 3) * 8;   // output col base (0..248)
    const int n8 = (tid & 7) * 8;    // node base within tile (0..56)

    float acc[8][8];
    #pragma unroll
    for (int oi = 0; oi < 8; oi++) {
        int c = o8 + oi;
        float b = (c < DOUT) ? brel[c] : bres[c - DOUT];
        #pragma unroll
        for (int nj = 0; nj < 8; nj++) acc[oi][nj] = b;
    }

    for (int t = 0; t < DIN / 32; t++) {
        __syncthreads();
        for (int i = tid; i < 64 * 32; i += 256) {
            int kk = i & 31, n = i >> 5;
            int node = m0 + n;
            fs[kk * 68 + n] = (node < N) ? feats[node * DIN + t * 32 + kk] : 0.f;
        }
        for (int i = tid; i < 256 * 32; i += 256) {
            int kk = i & 31, o = i >> 5;
            float v = (o < DOUT) ? Wrel[o * DIN + t * 32 + kk]
                                 : Wres[(o - DOUT) * DIN + t * 32 + kk];
            ws[kk * 260 + o] = v;
        }
        __syncthreads();

        #pragma unroll
        for (int kk = 0; kk < 32; kk++) {
            float4 w0 = *(const float4*)&ws[kk * 260 + o8];
            float4 w1 = *(const float4*)&ws[kk * 260 + o8 + 4];
            float4 f0 = *(const float4*)&fs[kk * 68 + n8];
            float4 f1 = *(const float4*)&fs[kk * 68 + n8 + 4];
            float wv[8] = {w0.x, w0.y, w0.z, w0.w, w1.x, w1.y, w1.z, w1.w};
            float fv[8] = {f0.x, f0.y, f0.z, f0.w, f1.x, f1.y, f1.z, f1.w};
            #pragma unroll
            for (int oi = 0; oi < 8; oi++)
                #pragma unroll
                for (int nj = 0; nj < 8; nj++)
                    acc[oi][nj] += wv[oi] * fv[nj];
        }
    }

    #pragma unroll
    for (int nj = 0; nj < 8; nj++) {
        int node = m0 + n8 + nj;
        if (node >= N) continue;
        #pragma unroll
        for (int oi = 0; oi < 8; oi += 4) {
            int c = o8 + oi;
            float4 v = make_float4(acc[oi][nj], acc[oi+1][nj], acc[oi+2][nj], acc[oi+3][nj]);
            if (c < DOUT) {
                *(float4*)&g_x[node * DOUT + c] = v;
            } else {
                v.x = fmaxf(v.x, 0.f); v.y = fmaxf(v.y, 0.f);
                v.z = fmaxf(v.z, 0.f); v.w = fmaxf(v.w, 0.f);
                *(float4*)&g_res[node * DOUT + (c - DOUT)] = v;
            }
        }
    }
}

// ---------------- K2a: histogram over dst -------------------------------------
__global__ __launch_bounds__(256)
void k_hist(const void* __restrict__ ei_raw, int E)
{
    int e = blockIdx.x * blockDim.x + threadIdx.x;
    if (e >= E) return;
    int d = g_is64 ? (int)((const long long*)ei_raw)[E + e]
                   : ((const int*)ei_raw)[E + e];
    atomicAdd(&g_cnt[d], 1);
}

// ---------------- K2b: 3-phase multi-block exclusive scan --------------------
__global__ __launch_bounds__(SCAN_BLK)
void k_scan1(int N)
{
    __shared__ int wsum[NWARPS];
    int i = blockIdx.x * SCAN_BLK + threadIdx.x;
    int wid = threadIdx.x >> 5, lane = threadIdx.x & 31;
    int v = (i < N) ? g_cnt[i] : 0;
    #pragma unroll
    for (int o = 16; o > 0; o >>= 1) v += __shfl_down_sync(0xffffffffu, v, o);
    if (lane == 0) wsum[wid] = v;
    __syncthreads();
    if (wid == 0) {                       // full warp participates (legal mask)
        int s = (lane < NWARPS) ? wsum[lane] : 0;
        #pragma unroll
        for (int o = 16; o > 0; o >>= 1) s += __shfl_down_sync(0xffffffffu, s, o);
        if (lane == 0) g_bsum[blockIdx.x] = s;
    }
}

__global__ __launch_bounds__(MAXB1)
void k_scan2(int nb, int N)
{
    __shared__ int ps[MAXB1];
    int t = threadIdx.x;
    int v = (t < nb) ? g_bsum[t] : 0;
    ps[t] = v;
    __syncthreads();
    #pragma unroll
    for (int o = 1; o < MAXB1; o <<= 1) {
        int y = 0;
        if (t >= o) y = ps[t - o];
        __syncthreads();
        if (t >= o) ps[t] += y;
        __syncthreads();
    }
    if (t < nb) g_boff[t] = ps[t] - v;      // exclusive
    if (t == MAXB1 - 1) g_off[N] = ps[MAXB1 - 1];
}

__global__ __launch_bounds__(SCAN_BLK)
void k_scan3(int N)
{
    __shared__ int wsum[NWARPS];
    int i = blockIdx.x * SCAN_BLK + threadIdx.x;
    int wid = threadIdx.x >> 5, lane = threadIdx.x & 31;
    int v = (i < N) ? g_cnt[i] : 0;
    int x = v;
    #pragma unroll
    for (int o = 1; o < 32; o <<= 1) {
        int y = __shfl_up_sync(0xffffffffu, x, o);
        if (lane >= o) x += y;
    }
    if (lane == 31) wsum[wid] = x;
    __syncthreads();
    if (wid == 0) {                       // full warp participates (legal mask)
        int s = (lane < NWARPS) ? wsum[lane] : 0;
        #pragma unroll
        for (int o = 1; o < 32; o <<= 1) {
            int y = __shfl_up_sync(0xffffffffu, s, o);
            if (lane >= o) s += y;
        }
        if (lane < NWARPS) wsum[lane] = s;
    }
    __syncthreads();
    int woff = (wid > 0) ? wsum[wid - 1] : 0;
    int excl = x - v + woff + g_boff[blockIdx.x];
    if (i < N) { g_off[i] = excl; g_cur[i] = excl; }
}

// ---------------- K2c: place edges into CSR + scatter edge_attr sums ---------
__global__ __launch_bounds__(256)
void k_place(const void* __restrict__ ei_raw, const float* __restrict__ eattr, int E)
{
    int e = blockIdx.x * blockDim.x + threadIdx.x;
    if (e >= E) return;
    int s, d;
    if (g_is64) {
        const long long* p = (const long long*)ei_raw;
        s = (int)p[e]; d = (int)p[E + e];
    } else {
        const int* p = (const int*)ei_raw;
        s = p[e]; d = p[E + e];
    }
    int pos = atomicAdd(&g_cur[d], 1);
    g_csr_src[pos] = s;

    const float4* a4 = (const float4*)&eattr[(size_t)e * EDIM];
    float* dst = &g_ea[(size_t)d * EDIM];
    red_add_v4(dst + 0,  a4[0]);
    red_add_v4(dst + 4,  a4[1]);
    red_add_v4(dst + 8,  a4[2]);
    red_add_v4(dst + 12, a4[3]);
}

// ---------------- K2d: pull aggregation fused with combine + BN partials ----
__global__ __launch_bounds__(256)
void k_pull(const float* __restrict__ We, const float* __restrict__ be, int N)
{
    __shared__ float s_sum[128];
    __shared__ float s_sq[128];
    int tid = threadIdx.x;
    if (tid < 128) { s_sum[tid] = 0.f; s_sq[tid] = 0.f; }
    __syncthreads();

    int warp = tid >> 5, lane = tid & 31;
    int n = blockIdx.x * 8 + warp;

    if (n < N) {
        const int j0 = g_off[n], j1 = g_off[n + 1];
        const int c0 = lane * 4;

        float4 acc = make_float4(0.f, 0.f, 0.f, 0.f);

        int j = j0;
        for (; j + 3 < j1; j += 4) {
            int s0 = g_csr_src[j],   s1 = g_csr_src[j+1];
            int s2 = g_csr_src[j+2], s3 = g_csr_src[j+3];
            float4 x0 = *(const float4*)&g_x[(size_t)s0 * DOUT + c0];
            float4 x1 = *(const float4*)&g_x[(size_t)s1 * DOUT + c0];
            float4 x2 = *(const float4*)&g_x[(size_t)s2 * DOUT + c0];
            float4 x3 = *(const float4*)&g_x[(size_t)s3 * DOUT + c0];
            acc.x += (x0.x + x1.x) + (x2.x + x3.x);
            acc.y += (x0.y + x1.y) + (x2.y + x3.y);
            acc.z += (x0.z + x1.z) + (x2.z + x3.z);
            acc.w += (x0.w + x1.w) + (x2.w + x3.w);
        }
        for (; j < j1; j++) {
            int s0 = g_csr_src[j];
            float4 x0 = *(const float4*)&g_x[(size_t)s0 * DOUT + c0];
            acc.x += x0.x; acc.y += x0.y; acc.z += x0.z; acc.w += x0.w;
        }

        // per-dst summed edge_attr (coalesced) -> broadcast to all lanes
        float ea = (lane < EDIM) ? g_ea[(size_t)n * EDIM + lane] : 0.f;
        float eav[EDIM];
        #pragma unroll
        for (int q = 0; q < EDIM; q++) eav[q] = __shfl_sync(0xffffffffu, ea, q);

        const float deg = (float)(j1 - j0);
        float4 b = *(const float4*)&be[c0];
        float4 elin = make_float4(b.x * deg, b.y * deg, b.z * deg, b.w * deg);

        const float4* W4 = (const float4*)We;  // row c: 4 float4 chunks
        #pragma unroll
        for (int q4 = 0; q4 < 4; q4++) {
            float4 w0 = W4[(c0 + 0) * 4 + q4];
            float4 w1 = W4[(c0 + 1) * 4 + q4];
            float4 w2 = W4[(c0 + 2) * 4 + q4];
            float4 w3 = W4[(c0 + 3) * 4 + q4];
            float e0v = eav[q4 * 4 + 0], e1v = eav[q4 * 4 + 1];
            float e2v = eav[q4 * 4 + 2], e3v = eav[q4 * 4 + 3];
            elin.x += w0.x * e0v + w0.y * e1v + w0.z * e2v + w0.w * e3v;
            elin.y += w1.x * e0v + w1.y * e1v + w1.z * e2v + w1.w * e3v;
            elin.z += w2.x * e0v + w2.y * e1v + w2.z * e2v + w2.w * e3v;
            elin.w += w3.x * e0v + w3.y * e1v + w3.z * e2v + w3.w * e3v;
        }

        float4 res = *(const float4*)&g_res[(size_t)n * DOUT + c0];
        float4 h;
        h.x = fmaxf(acc.x + elin.x, 0.f) + res.x;
        h.y = fmaxf(acc.y + elin.y, 0.f) + res.y;
        h.z = fmaxf(acc.z + elin.z, 0.f) + res.z;
        h.w = fmaxf(acc.w + elin.w, 0.f) + res.w;
        *(float4*)&g_h[(size_t)n * DOUT + c0] = h;

        atomicAdd(&s_sum[c0 + 0], h.x);
        atomicAdd(&s_sum[c0 + 1], h.y);
        atomicAdd(&s_sum[c0 + 2], h.z);
        atomicAdd(&s_sum[c0 + 3], h.w);
        atomicAdd(&s_sq[c0 + 0], h.x * h.x);
        atomicAdd(&s_sq[c0 + 1], h.y * h.y);
        atomicAdd(&s_sq[c0 + 2], h.z * h.z);
        atomicAdd(&s_sq[c0 + 3], h.w * h.w);
    }

    __syncthreads();
    if (tid < 128) {
        atomicAdd(&g_sum[tid],   s_sum[tid]);
        atomicAdd(&g_sumsq[tid], s_sq[tid]);
    }
}

// ---------------- K4: finalize BN stats --------------------------------------
__global__ void k4_stats(const float* __restrict__ gamma,
                         const float* __restrict__ beta, int N)
{
    int c = threadIdx.x;
    float invN = 1.f / (float)N;
    float mean = g_sum[c] * invN;
    float var  = g_sumsq[c] * invN - mean * mean;
    float rstd = rsqrtf(var + BN_EPS);
    float sc   = gamma[c] * rstd;
    g_scale[c] = sc;
    g_shift[c] = beta[c] - mean * sc;
}

// ---------------- K5: normalize ----------------------------------------------
__global__ __launch_bounds__(256)
void k5_norm(float* __restrict__ out, int total4)
{
    int idx = blockIdx.x * blockDim.x + threadIdx.x;
    if (idx >= total4) return;
    int c4 = (idx & (DOUT / 4 - 1)) * 4;
    float4 h  = *(const float4*)&g_h[idx * 4];
    float4 sc = *(const float4*)&g_scale[c4];
    float4 sh = *(const float4*)&g_shift[c4];
    float4 o;
    o.x = h.x * sc.x + sh.x;
    o.y = h.y * sc.y + sh.y;
    o.z = h.z * sc.z + sh.z;
    o.w = h.w * sc.w + sh.w;
    ((float4*)out)[idx] = o;
}

// ---------------- launch ------------------------------------------------------
extern "C" void kernel_launch(void* const* d_in, const int* in_sizes, int n_in,
                              void* d_out, int out_size)
{
    const float* feats = (const float*)d_in[0];
    const void*  ei    = d_in[1];
    const float* eattr = (const float*)d_in[2];
    const float* Wrel  = (const float*)d_in[3];
    const float* brel  = (const float*)d_in[4];
    const float* We    = (const float*)d_in[5];
    const float* be    = (const float*)d_in[6];
    const float* Wres  = (const float*)d_in[7];
    const float* bres  = (const float*)d_in[8];
    const float* gamma = (const float*)d_in[9];
    const float* beta  = (const float*)d_in[10];

    const int N = in_sizes[0] / DIN;
    const int E = in_sizes[2] / EDIM;
    const int nb = (N + SCAN_BLK - 1) / SCAN_BLK;

    k0_detect<<<1, 256>>>((const unsigned int*)ei);
    k1_node_gemm<<<(N + 63) / 64, 256>>>(feats, Wrel, brel, Wres, bres, N);
    k_hist<<<(E + 255) / 256, 256>>>(ei, E);
    k_scan1<<<nb, SCAN_BLK>>>(N);
    k_scan2<<<1, MAXB1>>>(nb, N);
    k_scan3<<<nb, SCAN_BLK>>>(N);
    k_place<<<(E + 255) / 256, 256>>>(ei, eattr, E);
    k_pull<<<(N + 7) / 8, 256>>>(We, be, N);
    k4_stats<<<1, 128>>>(gamma, beta, N);
    int total4 = N * DOUT / 4;
    k5_norm<<<(total4 + 255) / 256, 256>>>((float*)d_out, total4);
}